// round 3
// baseline (speedup 1.0000x reference)
#include <cuda_runtime.h>
#include <cuda_bf16.h>
#include <cstdint>

// Problem constants (shapes fixed by the reference)
#define MAXN 100000
#define MAXE 1600000
#define HDIM 128
#define FIN  9
#define GMAX 256

// -------- scratch (no cudaMalloc allowed) --------
// NOTE: never pass these as kernel args from host code — on GB300 the host
// shadow symbol is ATS-reachable and silently reads garbage. Device code
// references them directly.
__device__ __align__(128) float g_dinv[MAXN];            // deg -> rsqrt(deg)
__device__ __align__(128) float g_bufA[MAXN * HDIM];     // hw  (post-GEMM)
__device__ __align__(128) float g_bufB[MAXN * HDIM];     // agg (post-scatter)
__device__ int g_lo[GMAX];
__device__ int g_hi[GMAX];

// -------- init: deg=1 (self loop), graph bounds sentinel --------
__global__ void k_init(int n, int g) {
    int i = blockIdx.x * blockDim.x + threadIdx.x;
    if (i < n) g_dinv[i] = 1.0f;
    if (i < g) { g_lo[i] = 0x7fffffff; g_hi[i] = 0; }
}

// -------- degree count over edge dst (int32 indices) --------
__global__ void k_deg(const int* __restrict__ dst, int E) {
    int e = blockIdx.x * blockDim.x + threadIdx.x;
    if (e < E) atomicAdd(&g_dinv[dst[e]], 1.0f);
}

__global__ void k_rsqrt(int n) {
    int i = blockIdx.x * blockDim.x + threadIdx.x;
    if (i < n) g_dinv[i] = rsqrtf(g_dinv[i]);
}

// -------- graph node-range bounds (batch is sorted, int32) --------
__global__ void k_bounds(const int* __restrict__ batch, int n) {
    int i = blockIdx.x * blockDim.x + threadIdx.x;
    if (i >= n) return;
    int b = batch[i];
    atomicMin(&g_lo[b], i);
    atomicMax(&g_hi[b], i + 1);
}

// -------- GEMM: x[N,9] @ W1[9,128] -> bufA --------
__global__ void k_gemm_in(const float* __restrict__ x, const float* __restrict__ W, int n) {
    __shared__ float xr[2][FIN];
    int slot = threadIdx.x / HDIM;                 // 0..1
    int node = blockIdx.x * 2 + slot;
    int c = threadIdx.x % HDIM;
    if (node < n && c < FIN) xr[slot][c] = x[node * FIN + c];
    __syncthreads();
    if (node >= n) return;
    float s = 0.f;
#pragma unroll
    for (int k = 0; k < FIN; k++) s += xr[slot][k] * W[k * HDIM + c];
    g_bufA[node * HDIM + c] = s;
}

// -------- GEMM: relu(g_bufB)[N,128] @ W[128,128] -> bufA --------
// Reads g_bufB directly (device symbol), never via host-passed pointer.
__global__ void k_gemm_h(const float* __restrict__ W, int n) {
    __shared__ float row[2][HDIM];
    int slot = threadIdx.x / HDIM;
    int node = blockIdx.x * 2 + slot;
    int c = threadIdx.x % HDIM;
    if (node < n) {
        float v = g_bufB[node * HDIM + c];
        row[slot][c] = fmaxf(v, 0.0f);
    }
    __syncthreads();
    if (node >= n) return;
    float s = 0.f;
#pragma unroll 8
    for (int k = 0; k < HDIM; k++) s += row[slot][k] * W[k * HDIM + c];
    g_bufA[node * HDIM + c] = s;
}

// -------- self-loop + bias: bufB = bufA * dinv^2 + b --------
__global__ void k_self(const float* __restrict__ bias, int n) {
    int idx = blockIdx.x * blockDim.x + threadIdx.x;
    if (idx >= n * HDIM) return;
    int node = idx >> 7;
    int c = idx & (HDIM - 1);
    float d = g_dinv[node];
    g_bufB[idx] = g_bufA[idx] * d * d + bias[c];
}

// -------- edge scatter: bufB[dst] += bufA[src] * dinv[src]*dinv[dst] --------
// 32 threads per edge, each handles 4 contiguous floats via vector red.
__global__ void k_scatter(const int* __restrict__ src,
                          const int* __restrict__ dst, int E) {
    long long idx = (long long)blockIdx.x * blockDim.x + threadIdx.x;
    int e = (int)(idx >> 5);
    if (e >= E) return;
    int q = ((int)idx & 31) * 4;
    int s = __ldg(&src[e]);
    int d = __ldg(&dst[e]);
    float norm = g_dinv[s] * g_dinv[d];
    float4 v = *reinterpret_cast<const float4*>(&g_bufA[s * HDIM + q]);
    float* p = &g_bufB[d * HDIM + q];
    asm volatile("red.global.add.v4.f32 [%0], {%1,%2,%3,%4};"
                 :: "l"(p), "f"(v.x * norm), "f"(v.y * norm),
                    "f"(v.z * norm), "f"(v.w * norm)
                 : "memory");
}

// -------- pool (segment mean over sorted batch) + final linear --------
__global__ void k_pool(const float* __restrict__ lin_w,
                       const float* __restrict__ lin_b,
                       float* __restrict__ out) {
    int g = blockIdx.x;
    int c = threadIdx.x;  // HDIM threads
    int lo = g_lo[g], hi = g_hi[g];
    float s = 0.f;
    for (int node = lo; node < hi; node++) s += g_bufB[node * HDIM + c];
    float cnt = (float)(hi - lo > 0 ? hi - lo : 0);
    float pooled = s / fmaxf(cnt, 1.0f);
    __shared__ float red[HDIM];
    red[c] = pooled * lin_w[c];
    __syncthreads();
    for (int off = HDIM / 2; off > 0; off >>= 1) {
        if (c < off) red[c] += red[c + off];
        __syncthreads();
    }
    if (c == 0) out[g] = red[0] + lin_b[0];
}

extern "C" void kernel_launch(void* const* d_in, const int* in_sizes, int n_in,
                              void* d_out, int out_size) {
    const float* x     = (const float*)d_in[0];
    const int*   ei    = (const int*)d_in[1];   // [2, E] int32
    const int*   batch = (const int*)d_in[2];   // [N]    int32
    const float* W1 = (const float*)d_in[3];
    const float* b1 = (const float*)d_in[4];
    const float* W2 = (const float*)d_in[5];
    const float* b2 = (const float*)d_in[6];
    const float* W3 = (const float*)d_in[7];
    const float* b3 = (const float*)d_in[8];
    const float* lw = (const float*)d_in[9];
    const float* lb = (const float*)d_in[10];
    float* out = (float*)d_out;

    int N = in_sizes[0] / FIN;
    int E = in_sizes[1] / 2;
    int G = out_size;

    const int* src = ei;
    const int* dst = ei + E;

    // degrees + graph bounds
    k_init<<<(N + 255) / 256, 256>>>(N, G);
    k_deg<<<(E + 255) / 256, 256>>>(dst, E);
    k_rsqrt<<<(N + 255) / 256, 256>>>(N);
    k_bounds<<<(N + 255) / 256, 256>>>(batch, N);

    int gemm_blocks = (N + 1) / 2;
    long long scat_items = (long long)E * 32;
    int scat_blocks = (int)((scat_items + 255) / 256);
    int self_blocks = (N * HDIM + 255) / 256;

    // layer 1
    k_gemm_in<<<gemm_blocks, 256>>>(x, W1, N);
    k_self<<<self_blocks, 256>>>(b1, N);
    k_scatter<<<scat_blocks, 256>>>(src, dst, E);
    // layer 2 (relu fused into gemm read)
    k_gemm_h<<<gemm_blocks, 256>>>(W2, N);
    k_self<<<self_blocks, 256>>>(b2, N);
    k_scatter<<<scat_blocks, 256>>>(src, dst, E);
    // layer 3
    k_gemm_h<<<gemm_blocks, 256>>>(W3, N);
    k_self<<<self_blocks, 256>>>(b3, N);
    k_scatter<<<scat_blocks, 256>>>(src, dst, E);

    // pool + linear
    k_pool<<<G, HDIM>>>(lw, lb, out);
}

// round 4
// speedup vs baseline: 2.4402x; 2.4402x over previous
#include <cuda_runtime.h>
#include <cstdint>

#define MAXN 100000
#define MAXE 1600000
#define HDIM 128
#define FIN  9
#define GMAX 256
#define SCAN_B 256
#define MAXBLK 512   // max scan blocks (ceil(100000/256)=391)

// -------- scratch (device symbols only; NEVER pass from host — GB300 ATS trap) ----
__device__ __align__(128) float g_dinv[MAXN];
__device__ __align__(128) float g_bufA[MAXN * HDIM];   // hw (post-GEMM, pre-agg)
__device__ __align__(128) float g_bufB[MAXN * HDIM];   // layer output (post-agg)
__device__ __align__(128) float g_xa[MAXN * FIN];      // aggregated input features
__device__ int   g_degc[MAXN];
__device__ int   g_rowstart[MAXN + 1];
__device__ int   g_cursor[MAXN];
__device__ int   g_bsum[MAXBLK];
__device__ int   g_boff[MAXBLK];
__device__ int   g_csrc[MAXE];
__device__ float g_cnorm[MAXE];
__device__ int   g_lo[GMAX];
__device__ int   g_hi[GMAX];

// ======================= setup =======================
__global__ void k_clear(int n, int g) {
    int i = blockIdx.x * blockDim.x + threadIdx.x;
    if (i < n) g_degc[i] = 0;
    if (i < g) { g_lo[i] = 0; g_hi[i] = 0; }
}

__global__ void k_deg(const int* __restrict__ dst, int E) {
    int e = blockIdx.x * blockDim.x + threadIdx.x;
    if (e < E) atomicAdd(&g_degc[dst[e]], 1);
}

__global__ void k_dinv(int n) {
    int i = blockIdx.x * blockDim.x + threadIdx.x;
    if (i < n) g_dinv[i] = rsqrtf((float)(g_degc[i] + 1));  // +1 self loop
}

// block-local exclusive scan of degc, block sums to g_bsum
__global__ void k_scan1(int n) {
    __shared__ int sh[SCAN_B];
    int i = blockIdx.x * SCAN_B + threadIdx.x;
    int v = (i < n) ? g_degc[i] : 0;
    sh[threadIdx.x] = v;
    __syncthreads();
    for (int off = 1; off < SCAN_B; off <<= 1) {
        int t = (threadIdx.x >= (unsigned)off) ? sh[threadIdx.x - off] : 0;
        __syncthreads();
        sh[threadIdx.x] += t;
        __syncthreads();
    }
    if (i < n) g_rowstart[i] = sh[threadIdx.x] - v;     // local exclusive
    if (threadIdx.x == SCAN_B - 1) g_bsum[blockIdx.x] = sh[SCAN_B - 1];
}

// scan the block sums (single block, nb <= 512)
__global__ void k_scan2(int nb) {
    __shared__ int sh[MAXBLK];
    int v = (threadIdx.x < (unsigned)nb) ? g_bsum[threadIdx.x] : 0;
    sh[threadIdx.x] = v;
    __syncthreads();
    for (int off = 1; off < MAXBLK; off <<= 1) {
        int t = (threadIdx.x >= (unsigned)off) ? sh[threadIdx.x - off] : 0;
        __syncthreads();
        sh[threadIdx.x] += t;
        __syncthreads();
    }
    if (threadIdx.x < (unsigned)nb) g_boff[threadIdx.x] = sh[threadIdx.x] - v;
}

// finalize rowstart, init cursors
__global__ void k_scan3(int n, int E) {
    int i = blockIdx.x * blockDim.x + threadIdx.x;
    if (i < n) {
        int r = g_rowstart[i] + g_boff[i >> 8];
        g_rowstart[i] = r;
        g_cursor[i] = r;
    } else if (i == n) {
        g_rowstart[n] = E;
    }
}

// fill CSR (src + precomputed norm per edge)
__global__ void k_fill(const int* __restrict__ src, const int* __restrict__ dst, int E) {
    int e = blockIdx.x * blockDim.x + threadIdx.x;
    if (e >= E) return;
    int s = src[e], d = dst[e];
    int pos = atomicAdd(&g_cursor[d], 1);
    g_csrc[pos] = s;
    g_cnorm[pos] = g_dinv[s] * g_dinv[d];
}

// graph bounds via boundary detection (batch sorted)
__global__ void k_bounds(const int* __restrict__ batch, int n) {
    int i = blockIdx.x * blockDim.x + threadIdx.x;
    if (i >= n) return;
    int b = batch[i];
    if (i == 0) g_lo[b] = 0;
    else {
        int pb = batch[i - 1];
        if (pb != b) { g_lo[b] = i; g_hi[pb] = i; }
    }
    if (i == n - 1) g_hi[b] = n;
}

// ======================= layer 1: aggregate x (9 cols), then GEMM ============
// warp per node, lanes 0..8 carry one feature each
__global__ void k_aggx(const float* __restrict__ x, int n) {
    int w = (blockIdx.x * blockDim.x + threadIdx.x) >> 5;
    if (w >= n) return;
    int lane = threadIdx.x & 31;
    int rs = g_rowstart[w], re = g_rowstart[w + 1];
    float di = g_dinv[w];
    float acc = 0.f;
    if (lane < FIN) acc = x[w * FIN + lane] * di * di;
    for (int j = rs; j < re; j++) {
        int s = g_csrc[j];
        float wt = g_cnorm[j];
        if (lane < FIN) acc += x[s * FIN + lane] * wt;
    }
    if (lane < FIN) g_xa[w * FIN + lane] = acc;
}

// bufB = xa @ W1 + b1   (aggregation already applied)
__global__ void k_gemm_in(const float* __restrict__ W, const float* __restrict__ bias, int n) {
    __shared__ float xr[2][FIN];
    int slot = threadIdx.x / HDIM;
    int node = blockIdx.x * 2 + slot;
    int c = threadIdx.x % HDIM;
    if (node < n && c < FIN) xr[slot][c] = g_xa[node * FIN + c];
    __syncthreads();
    if (node >= n) return;
    float s = bias[c];
#pragma unroll
    for (int k = 0; k < FIN; k++) s += xr[slot][k] * W[k * HDIM + c];
    g_bufB[node * HDIM + c] = s;
}

// ======================= hidden GEMM: bufA = relu(bufB) @ W ==================
// block: 256 threads = 8 row-threads x 32 col-threads; tile 32 rows x 128 cols
// each thread computes 4 rows x 4 cols. W read via LDG.128 (L1-resident 64KB).
#define GR 32            // rows per block
#define RPAD 36          // rT row stride (16B-aligned, low-conflict)
__global__ void __launch_bounds__(256) k_gemm_h(const float* __restrict__ W, int n) {
    __shared__ float rT[HDIM * RPAD];   // rT[k][r] transposed inputs, 18.4KB
    int node0 = blockIdx.x * GR;
    // load 32 rows x 128 cols with relu, store transposed
    for (int idx = threadIdx.x; idx < GR * HDIM; idx += 256) {
        int r = idx >> 7, c = idx & (HDIM - 1);
        float v = 0.f;
        if (node0 + r < n) v = fmaxf(g_bufB[(node0 + r) * HDIM + c], 0.f);
        rT[c * RPAD + r] = v;
    }
    __syncthreads();

    int ct = threadIdx.x & 31;   // 32 col-threads -> 128 cols
    int rt = threadIdx.x >> 5;   // 8  row-threads -> 32 rows
    float acc[4][4];
#pragma unroll
    for (int i = 0; i < 4; i++)
#pragma unroll
        for (int j = 0; j < 4; j++) acc[i][j] = 0.f;

#pragma unroll 2
    for (int k = 0; k < HDIM; k++) {
        float4 a = *reinterpret_cast<const float4*>(&rT[k * RPAD + rt * 4]);  // broadcast
        float4 wv = __ldg(reinterpret_cast<const float4*>(&W[k * HDIM + ct * 4]));
        acc[0][0] += a.x * wv.x; acc[0][1] += a.x * wv.y; acc[0][2] += a.x * wv.z; acc[0][3] += a.x * wv.w;
        acc[1][0] += a.y * wv.x; acc[1][1] += a.y * wv.y; acc[1][2] += a.y * wv.z; acc[1][3] += a.y * wv.w;
        acc[2][0] += a.z * wv.x; acc[2][1] += a.z * wv.y; acc[2][2] += a.z * wv.z; acc[2][3] += a.z * wv.w;
        acc[3][0] += a.w * wv.x; acc[3][1] += a.w * wv.y; acc[3][2] += a.w * wv.z; acc[3][3] += a.w * wv.w;
    }
#pragma unroll
    for (int i = 0; i < 4; i++) {
        int node = node0 + rt * 4 + i;
        if (node < n) {
            float4 o = make_float4(acc[i][0], acc[i][1], acc[i][2], acc[i][3]);
            *reinterpret_cast<float4*>(&g_bufA[node * HDIM + ct * 4]) = o;
        }
    }
}

// ======================= hidden aggregate: bufB = Â bufA + bias ==============
// warp per node, each lane owns a float4 column slice; atomic-free gather
__global__ void k_gather_h(const float* __restrict__ bias, int n) {
    int w = (blockIdx.x * blockDim.x + threadIdx.x) >> 5;
    if (w >= n) return;
    int lane = threadIdx.x & 31;
    int q = lane * 4;
    int rs = g_rowstart[w], re = g_rowstart[w + 1];
    float di = g_dinv[w];

    float4 self = *reinterpret_cast<const float4*>(&g_bufA[w * HDIM + q]);
    float d2 = di * di;
    float4 acc = make_float4(self.x * d2, self.y * d2, self.z * d2, self.w * d2);

    int j = rs;
    for (; j + 1 < re; j += 2) {   // 2-way unroll for MLP
        int   s0 = g_csrc[j],     s1 = g_csrc[j + 1];
        float w0 = g_cnorm[j],    w1 = g_cnorm[j + 1];
        float4 v0 = *reinterpret_cast<const float4*>(&g_bufA[s0 * HDIM + q]);
        float4 v1 = *reinterpret_cast<const float4*>(&g_bufA[s1 * HDIM + q]);
        acc.x += v0.x * w0 + v1.x * w1;
        acc.y += v0.y * w0 + v1.y * w1;
        acc.z += v0.z * w0 + v1.z * w1;
        acc.w += v0.w * w0 + v1.w * w1;
    }
    if (j < re) {
        int s0 = g_csrc[j]; float w0 = g_cnorm[j];
        float4 v0 = *reinterpret_cast<const float4*>(&g_bufA[s0 * HDIM + q]);
        acc.x += v0.x * w0; acc.y += v0.y * w0; acc.z += v0.z * w0; acc.w += v0.w * w0;
    }
    float4 b = __ldg(reinterpret_cast<const float4*>(&bias[q]));
    acc.x += b.x; acc.y += b.y; acc.z += b.z; acc.w += b.w;
    *reinterpret_cast<float4*>(&g_bufB[w * HDIM + q]) = acc;
}

// ======================= pool + final linear =======================
__global__ void k_pool(const float* __restrict__ lin_w,
                       const float* __restrict__ lin_b,
                       float* __restrict__ out) {
    int g = blockIdx.x;
    int c = threadIdx.x;  // HDIM threads
    int lo = g_lo[g], hi = g_hi[g];
    float s = 0.f;
    for (int node = lo; node < hi; node++) s += g_bufB[node * HDIM + c];
    float cnt = (float)(hi - lo);
    float pooled = s / fmaxf(cnt, 1.0f);
    __shared__ float red[HDIM];
    red[c] = pooled * lin_w[c];
    __syncthreads();
    for (int off = HDIM / 2; off > 0; off >>= 1) {
        if (c < off) red[c] += red[c + off];
        __syncthreads();
    }
    if (c == 0) out[g] = red[0] + lin_b[0];
}

extern "C" void kernel_launch(void* const* d_in, const int* in_sizes, int n_in,
                              void* d_out, int out_size) {
    const float* x     = (const float*)d_in[0];
    const int*   ei    = (const int*)d_in[1];   // [2,E] int32
    const int*   batch = (const int*)d_in[2];   // [N]   int32
    const float* W1 = (const float*)d_in[3];
    const float* b1 = (const float*)d_in[4];
    const float* W2 = (const float*)d_in[5];
    const float* b2 = (const float*)d_in[6];
    const float* W3 = (const float*)d_in[7];
    const float* b3 = (const float*)d_in[8];
    const float* lw = (const float*)d_in[9];
    const float* lb = (const float*)d_in[10];
    float* out = (float*)d_out;

    int N = in_sizes[0] / FIN;
    int E = in_sizes[1] / 2;
    int G = out_size;

    const int* src = ei;
    const int* dst = ei + E;

    int nb  = (N + SCAN_B - 1) / SCAN_B;
    int eb  = (E + 255) / 256;
    int wb  = (N * 32 + 255) / 256;          // warp-per-node grids
    int gb  = (N + GR - 1) / GR;             // gemm_h blocks
    int inb = (N + 1) / 2;

    // ---- CSR build + bounds (once per launch, reused 3x) ----
    k_clear<<<nb, SCAN_B>>>(N, G);
    k_deg<<<eb, 256>>>(dst, E);
    k_dinv<<<nb, SCAN_B>>>(N);
    k_scan1<<<nb, SCAN_B>>>(N);
    k_scan2<<<1, MAXBLK>>>(nb);
    k_scan3<<<(N + 256) / 256, 256>>>(N, E);
    k_fill<<<eb, 256>>>(src, dst, E);
    k_bounds<<<nb, SCAN_B>>>(batch, N);

    // ---- layer 1: (Â X) W1 + b1 ----
    k_aggx<<<wb, 256>>>(x, N);
    k_gemm_in<<<inb, 256>>>(W1, b1, N);
    // ---- layer 2 ----
    k_gemm_h<<<gb, 256>>>(W2, N);
    k_gather_h<<<wb, 256>>>(b2, N);
    // ---- layer 3 ----
    k_gemm_h<<<gb, 256>>>(W3, N);
    k_gather_h<<<wb, 256>>>(b3, N);

    // ---- pool + linear ----
    k_pool<<<G, HDIM>>>(lw, lb, out);
}